// round 14
// baseline (speedup 1.0000x reference)
#include <cuda_runtime.h>
#include <math.h>

#define BATCH 1024
#define NIN   512
#define NHID  256

// ---------------------------------------------------------------------------
// Device-global scratch (no allocation allowed anywhere).
// ---------------------------------------------------------------------------
__device__ unsigned      g_mT1[16 * NHID];   // transposed bitmask [w][node], layer1
__device__ unsigned      g_mT2[8 * NIN];     // transposed bitmask [w][node], layer2
__device__ unsigned char g_sel1[NHID];       // 1 = max-node, 0 = min-node
__device__ unsigned char g_sel2[NIN];

// ---------------------------------------------------------------------------
// Gumbel hard-select: forward value is exactly one-hot of argmax(logits + g).
// ---------------------------------------------------------------------------
__device__ __forceinline__ float gumbel_f(float u) {
    u = fminf(fmaxf(u, 1e-10f), 1.0f);
    return -logf(-logf(u));
}

// Per-warp mask dtype detection: 2 lane-parallel loads + ballots.
__device__ __forceinline__ int warp_detect(const void* p, int lane) {
    const unsigned* pw = (const unsigned*)p;
    unsigned a = pw[lane], b = pw[lane + 32];
    bool i32 = (a <= 1u) && (b <= 1u);
    bool f32 = (a == 0u || a == 0x3F800000u) && (b == 0u || b == 0x3F800000u);
    i32 = __all_sync(0xffffffffu, i32);
    f32 = __all_sync(0xffffffffu, f32);
    return i32 ? 2 : (f32 ? 3 : 1);
}

__device__ __forceinline__ bool mask_at(const void* p, int mode, int e) {
    if (mode == 2) return ((const int*)p)[e] != 0;
    if (mode == 3) return ((const float*)p)[e] != 0.0f;
    return ((const unsigned char*)p)[e] != 0;
}

// Prep: blocks 0..255 pack masks (one warp -> 4 words, coalesced + MLP);
// block 256 computes node sel for both layers.
__global__ void __launch_bounds__(256) prep_kernel(const void* __restrict__ m1,
                                                   const void* __restrict__ m2,
                                                   const float* __restrict__ logits1,
                                                   const float* __restrict__ u1,
                                                   const float* __restrict__ logits2,
                                                   const float* __restrict__ u2) {
    if (blockIdx.x == 256) {
        int n = threadIdx.x;
        {
            float z0 = logits1[2 * n]     + gumbel_f(u1[2 * n]);
            float z1 = logits1[2 * n + 1] + gumbel_f(u1[2 * n + 1]);
            g_sel1[n] = (z1 > z0) ? 1 : 0;
        }
        #pragma unroll
        for (int q = 0; q < 2; q++) {
            int j = q * 256 + n;
            float z0 = logits2[2 * j]     + gumbel_f(u2[2 * j]);
            float z1 = logits2[2 * j + 1] + gumbel_f(u2[2 * j + 1]);
            g_sel2[j] = (z1 > z0) ? 1 : 0;
        }
        return;
    }
    const int gw   = (blockIdx.x * 256 + threadIdx.x) >> 5;   // 0..2047
    const int lane = threadIdx.x & 31;
    if (gw < 1024) {
        const int mode = warp_detect(m1, lane);
        #pragma unroll
        for (int q = 0; q < 4; q++) {
            int wi = gw * 4 + q;
            int node = wi >> 4, w = wi & 15;
            bool b = mask_at(m1, mode, node * NIN + w * 32 + lane);
            unsigned bits = __ballot_sync(0xffffffffu, b);
            if (lane == 0) g_mT1[w * NHID + node] = bits;
        }
    } else {
        const int mode = warp_detect(m2, lane);
        #pragma unroll
        for (int q = 0; q < 4; q++) {
            int wi = (gw - 1024) * 4 + q;
            int node = wi >> 3, w = wi & 7;
            bool b = mask_at(m2, mode, node * NHID + w * 32 + lane);
            unsigned bits = __ballot_sync(0xffffffffu, b);
            if (lane == 0) g_mT2[w * NIN + node] = bits;
        }
    }
}

// ---------------------------------------------------------------------------
// Warp bitonic sort of 32*R u32 keys, ascending. Element i = lane*R + r.
// In-register passes exist ONLY for J < R (compile-time guarded).
// ---------------------------------------------------------------------------
template<int R, int J>
__device__ __forceinline__ void inreg_pass(unsigned* key, int lane, int k) {
    if constexpr (J < R) {
        if (2 * J > k) return;
        #pragma unroll
        for (int r = 0; r < R; r++) {
            if ((r & J) == 0) {
                bool asc = (((unsigned)(lane * R + r) & (unsigned)k) == 0);
                unsigned a = key[r], b = key[r + J];
                unsigned mn = a < b ? a : b;
                unsigned mx = a < b ? b : a;
                key[r]     = asc ? mn : mx;
                key[r + J] = asc ? mx : mn;
            }
        }
    }
}

template<int R>
__device__ __forceinline__ void bitonic_sort_warp(unsigned* key) {
    const int lane = threadIdx.x & 31;
    const int N = 32 * R;
    for (int k = 2; k <= N; k <<= 1) {
        for (int m = (k >> 1) / R; m >= 1; m >>= 1) {
            #pragma unroll
            for (int r = 0; r < R; r++) {
                unsigned a = key[r];
                unsigned b = __shfl_xor_sync(0xffffffffu, a, m);
                bool asc   = (((unsigned)(lane * R + r) & (unsigned)k) == 0);
                bool lower = ((lane & m) == 0);
                unsigned mn = a < b ? a : b;
                unsigned mx = a < b ? b : a;
                key[r] = (lower == asc) ? mn : mx;
            }
        }
        inreg_pass<R, 8>(key, lane, k);
        inreg_pass<R, 4>(key, lane, k);
        inreg_pass<R, 2>(key, lane, k);
        inreg_pass<R, 1>(key, lane, k);
    }
}

// Ascending bitonic MERGE of 32*R elements held by one warp (j = 16R..1).
template<int R, int J>
__device__ __forceinline__ void inreg_merge_asc(unsigned* key) {
    if constexpr (J < R) {
        #pragma unroll
        for (int r = 0; r < R; r++) {
            if ((r & J) == 0) {
                unsigned a = key[r], b = key[r + J];
                key[r]     = a < b ? a : b;
                key[r + J] = a < b ? b : a;
            }
        }
    }
}

template<int R>
__device__ __forceinline__ void bitonic_merge_asc(unsigned* key) {
    const int lane = threadIdx.x & 31;
    #pragma unroll
    for (int m = 16; m >= 1; m >>= 1) {
        #pragma unroll
        for (int r = 0; r < R; r++) {
            unsigned a = key[r];
            unsigned b = __shfl_xor_sync(0xffffffffu, a, m);
            bool lower = ((lane & m) == 0);
            unsigned mn = a < b ? a : b;
            unsigned mx = a < b ? b : a;
            key[r] = lower ? mn : mx;
        }
    }
    inreg_merge_asc<R, 8>(key);
    inreg_merge_asc<R, 4>(key);
    inreg_merge_asc<R, 2>(key);
    inreg_merge_asc<R, 1>(key);
}

template<int R>
__device__ __forceinline__ void invert_keys(unsigned* key) {
    #pragma unroll
    for (int r = 0; r < R; r++) key[r] = ~key[r];
}

// One cross-warp exchange step of the bitonic merge tree:
// read partner warp's keys from src, keep min/max, optionally finish with a
// warp-local merge (direction desc), store to dst. Caller syncs around it.
template<int R, bool DO_MERGE>
__device__ __forceinline__ void xstep(unsigned* key, const unsigned* src, unsigned* dst,
                                      int w, int lane, int pxor, bool desc) {
    const int EPW = 32 * R;
    const int pw = w ^ pxor;
    const bool keepmin = ((w < pw) != desc);
    #pragma unroll
    for (int r = 0; r < R; r++) {
        unsigned p = src[pw * EPW + lane * R + r];
        unsigned a = key[r];
        key[r] = keepmin ? (a < p ? a : p) : (a > p ? a : p);
    }
    if constexpr (DO_MERGE) {
        if (desc) invert_keys<R>(key);
        bitonic_merge_asc<R>(key);
        if (desc) invert_keys<R>(key);
    }
    #pragma unroll
    for (int r = 0; r < R; r++) dst[w * EPW + lane * R + r] = key[r];
}

// ---------------------------------------------------------------------------
// Mega-fused kernel: 256-thread blocks (8 warps), ONE row per block, 1024
// blocks -> ~55 warps/SM. ALL warps cooperate in every sort (8-warp bitonic
// merge tree, double-buffered smem exchanges) and every walk. Masks probed
// via LDG (32 KB, L1-resident after warm-up).
// ---------------------------------------------------------------------------
__global__ void __launch_bounds__(256) mega_kernel(const float* __restrict__ x,
                                                   float* __restrict__ out) {
    __shared__ unsigned      bufA[NIN];     // 2 KB — sort exchange / keys
    __shared__ unsigned      bufB[NIN];     // 2 KB
    __shared__ float         vals[NIN];     // 2 KB
    __shared__ float         hrow[NHID];    // 1 KB
    __shared__ unsigned char sel1[NHID];
    __shared__ unsigned char sel2[NIN];

    const int tid  = threadIdx.x;      // 0..255
    const int w    = tid >> 5;         // warp 0..7
    const int lane = tid & 31;
    const int row  = blockIdx.x;

    // ============ Layer-1 sort: local R=2 sorts (64 elems/warp) ==============
    unsigned key[2];
    {
        const float* src = x + (size_t)row * NIN + w * 64 + lane * 2;
        float2 v = *(const float2*)src;
        *(float2*)(&vals[w * 64 + lane * 2]) = v;
        key[0] = (__float_as_uint(v.x) & ~(unsigned)(NIN - 1)) | (unsigned)(w * 64 + lane * 2);
        key[1] = (__float_as_uint(v.y) & ~(unsigned)(NIN - 1)) | (unsigned)(w * 64 + lane * 2 + 1);

        // sel staging (precomputed by prep)
        if (tid < 64)  ((unsigned*)sel1)[tid] = ((const unsigned*)g_sel1)[tid];
        if (tid < 128) ((unsigned*)sel2)[tid] = ((const unsigned*)g_sel2)[tid];

        if (w & 1) invert_keys<2>(key);
        bitonic_sort_warp<2>(key);
        if (w & 1) invert_keys<2>(key);    // odd warps descending
        key[0] = key[0]; // keep in regs
        bufA[w * 64 + lane * 2]     = key[0];
        bufA[w * 64 + lane * 2 + 1] = key[1];
    }
    __syncthreads();
    // k=128: j=64 (w^1) + local merge
    xstep<2, true >(key, bufA, bufB, w, lane, 1, (w >> 1) & 1);
    __syncthreads();
    // k=256: j=128 (w^2)
    xstep<2, false>(key, bufB, bufA, w, lane, 2, (w >> 2) & 1);
    __syncthreads();
    // k=256: j=64 (w^1) + local merge
    xstep<2, true >(key, bufA, bufB, w, lane, 1, (w >> 2) & 1);
    __syncthreads();
    // k=512: j=256 (w^4)
    xstep<2, false>(key, bufB, bufA, w, lane, 4, false);
    __syncthreads();
    // k=512: j=128 (w^2)
    xstep<2, false>(key, bufA, bufB, w, lane, 2, false);
    __syncthreads();
    // k=512: j=64 (w^1) + local merge  -> final keys in bufA
    xstep<2, true >(key, bufB, bufA, w, lane, 1, false);
    __syncthreads();

    // ============ Layer-1 walk: 1 node-chain per thread (2-probe unroll) =====
    {
        const int node = tid;
        const bool s = sel1[node] != 0;
        float v = s ? 0.0f : 1.0f;     // empty-mask identity
        bool  f = false;
        for (int t = 0; t < NIN && !f; t += 2) {
            int t0 = s ? (NIN - 1) - t : t;
            int t1 = s ? (NIN - 2) - t : t + 1;
            int i0 = (int)(bufA[t0] & (unsigned)(NIN - 1));
            int i1 = (int)(bufA[t1] & (unsigned)(NIN - 1));
            unsigned m0 = g_mT1[(i0 >> 5) * NHID + node];   // coalesced, L1-resident
            unsigned m1 = g_mT1[(i1 >> 5) * NHID + node];
            bool h0 = (m0 >> (i0 & 31)) & 1u;
            bool h1 = (m1 >> (i1 & 31)) & 1u;
            if (h0)      { v = vals[i0]; f = true; }
            else if (h1) { v = vals[i1]; f = true; }
        }
        hrow[node] = fmaxf(v, 0.0f);
    }
    __syncthreads();

    // ============ Layer-2 sort: 8-warp, 32 elems/warp (R=1) ==================
    unsigned k2[1];
    {
        int c = w * 32 + lane;
        k2[0] = (__float_as_uint(hrow[c]) & ~(unsigned)(NHID - 1)) | (unsigned)c;
        if (w & 1) invert_keys<1>(k2);
        bitonic_sort_warp<1>(k2);
        if (w & 1) invert_keys<1>(k2);
        bufA[c] = k2[0];
    }
    __syncthreads();
    // k=64: j=32 (w^1) + local merge
    xstep<1, true >(k2, bufA, bufB, w, lane, 1, (w >> 1) & 1);
    __syncthreads();
    // k=128: j=64 (w^2)
    xstep<1, false>(k2, bufB, bufA, w, lane, 2, (w >> 2) & 1);
    __syncthreads();
    // k=128: j=32 (w^1) + local merge
    xstep<1, true >(k2, bufA, bufB, w, lane, 1, (w >> 2) & 1);
    __syncthreads();
    // k=256: j=128 (w^4)
    xstep<1, false>(k2, bufB, bufA, w, lane, 4, false);
    __syncthreads();
    // k=256: j=64 (w^2)
    xstep<1, false>(k2, bufA, bufB, w, lane, 2, false);
    __syncthreads();
    // k=256: j=32 (w^1) + local merge -> final keys in bufA
    xstep<1, true >(k2, bufB, bufA, w, lane, 1, false);
    __syncthreads();

    // ============ Layer-2 walk: 2 node-chains per thread ======================
    {
        bool s[2]; float v[2]; bool f[2];
        #pragma unroll
        for (int c = 0; c < 2; c++) {
            int node = c * 256 + tid;
            s[c] = sel2[node] != 0;
            v[c] = s[c] ? 0.0f : 1.0f;
            f[c] = false;
        }
        for (int t = 0; t < NHID; t++) {
            int iA = (int)(bufA[t] & (unsigned)(NHID - 1));
            int iB = (int)(bufA[(NHID - 1) - t] & (unsigned)(NHID - 1));
            bool alldone = true;
            #pragma unroll
            for (int c = 0; c < 2; c++) {
                if (!f[c]) {
                    int node = c * 256 + tid;
                    int idx  = s[c] ? iB : iA;
                    unsigned m = g_mT2[(idx >> 5) * NIN + node];    // L1-resident
                    if ((m >> (idx & 31)) & 1u) { v[c] = hrow[idx]; f[c] = true; }
                }
                alldone &= f[c];
            }
            if (alldone) break;
        }
        #pragma unroll
        for (int c = 0; c < 2; c++)
            out[(size_t)row * NIN + c * 256 + tid] = fmaxf(v[c], 0.0f);
    }
}

// ---------------------------------------------------------------------------
// kernel_launch: prep (masks + sel) -> mega (both layers). Two launches.
// ---------------------------------------------------------------------------
extern "C" void kernel_launch(void* const* d_in, const int* in_sizes, int n_in,
                              void* d_out, int out_size) {
    const float* x       = (const float*)d_in[0];
    const float* logits1 = (const float*)d_in[1];
    const float* u1      = (const float*)d_in[2];
    const float* logits2 = (const float*)d_in[3];
    const float* u2      = (const float*)d_in[4];
    const void*  mask1   = d_in[5];
    const void*  mask2   = d_in[6];
    float* out = (float*)d_out;
    (void)in_sizes; (void)n_in; (void)out_size;

    prep_kernel<<<257, 256>>>(mask1, mask2, logits1, u1, logits2, u2);
    mega_kernel<<<BATCH, 256>>>(x, out);
}

// round 15
// speedup vs baseline: 1.1085x; 1.1085x over previous
#include <cuda_runtime.h>
#include <math.h>

#define BATCH 1024
#define NIN   512
#define NHID  256

// ---------------------------------------------------------------------------
// Device-global scratch (no allocation allowed anywhere).
// ---------------------------------------------------------------------------
__device__ unsigned      g_mT1[16 * NHID];   // transposed bitmask [w][node], layer1
__device__ unsigned      g_mT2[8 * NIN];     // transposed bitmask [w][node], layer2
__device__ unsigned char g_sel1[NHID];       // 1 = max-node, 0 = min-node
__device__ unsigned char g_sel2[NIN];

// ---------------------------------------------------------------------------
// Gumbel hard-select: forward value is exactly one-hot of argmax(logits + g).
// ---------------------------------------------------------------------------
__device__ __forceinline__ float gumbel_f(float u) {
    u = fminf(fmaxf(u, 1e-10f), 1.0f);
    return -logf(-logf(u));
}

// Per-warp mask dtype detection: 2 lane-parallel loads + ballots.
__device__ __forceinline__ int warp_detect(const void* p, int lane) {
    const unsigned* pw = (const unsigned*)p;
    unsigned a = pw[lane], b = pw[lane + 32];
    bool i32 = (a <= 1u) && (b <= 1u);
    bool f32 = (a == 0u || a == 0x3F800000u) && (b == 0u || b == 0x3F800000u);
    i32 = __all_sync(0xffffffffu, i32);
    f32 = __all_sync(0xffffffffu, f32);
    return i32 ? 2 : (f32 ? 3 : 1);
}

__device__ __forceinline__ bool mask_at(const void* p, int mode, int e) {
    if (mode == 2) return ((const int*)p)[e] != 0;
    if (mode == 3) return ((const float*)p)[e] != 0.0f;
    return ((const unsigned char*)p)[e] != 0;
}

// Prep: blocks 0..255 pack masks (one warp -> 4 words, coalesced + MLP);
// block 256 computes node sel for both layers.
__global__ void __launch_bounds__(256) prep_kernel(const void* __restrict__ m1,
                                                   const void* __restrict__ m2,
                                                   const float* __restrict__ logits1,
                                                   const float* __restrict__ u1,
                                                   const float* __restrict__ logits2,
                                                   const float* __restrict__ u2) {
    if (blockIdx.x == 256) {
        int n = threadIdx.x;
        {
            float z0 = logits1[2 * n]     + gumbel_f(u1[2 * n]);
            float z1 = logits1[2 * n + 1] + gumbel_f(u1[2 * n + 1]);
            g_sel1[n] = (z1 > z0) ? 1 : 0;
        }
        #pragma unroll
        for (int q = 0; q < 2; q++) {
            int j = q * 256 + n;
            float z0 = logits2[2 * j]     + gumbel_f(u2[2 * j]);
            float z1 = logits2[2 * j + 1] + gumbel_f(u2[2 * j + 1]);
            g_sel2[j] = (z1 > z0) ? 1 : 0;
        }
        return;
    }
    const int gw   = (blockIdx.x * 256 + threadIdx.x) >> 5;   // 0..2047
    const int lane = threadIdx.x & 31;
    if (gw < 1024) {
        const int mode = warp_detect(m1, lane);
        #pragma unroll
        for (int q = 0; q < 4; q++) {
            int wi = gw * 4 + q;
            int node = wi >> 4, w = wi & 15;
            bool b = mask_at(m1, mode, node * NIN + w * 32 + lane);
            unsigned bits = __ballot_sync(0xffffffffu, b);
            if (lane == 0) g_mT1[w * NHID + node] = bits;
        }
    } else {
        const int mode = warp_detect(m2, lane);
        #pragma unroll
        for (int q = 0; q < 4; q++) {
            int wi = (gw - 1024) * 4 + q;
            int node = wi >> 3, w = wi & 7;
            bool b = mask_at(m2, mode, node * NHID + w * 32 + lane);
            unsigned bits = __ballot_sync(0xffffffffu, b);
            if (lane == 0) g_mT2[w * NIN + node] = bits;
        }
    }
}

// ---------------------------------------------------------------------------
// Warp bitonic sort of 32*R u32 keys, ascending. Element i = lane*R + r.
// In-register passes exist ONLY for J < R (compile-time guarded).
// ---------------------------------------------------------------------------
template<int R, int J>
__device__ __forceinline__ void inreg_pass(unsigned* key, int lane, int k) {
    if constexpr (J < R) {
        if (2 * J > k) return;
        #pragma unroll
        for (int r = 0; r < R; r++) {
            if ((r & J) == 0) {
                bool asc = (((unsigned)(lane * R + r) & (unsigned)k) == 0);
                unsigned a = key[r], b = key[r + J];
                unsigned mn = a < b ? a : b;
                unsigned mx = a < b ? b : a;
                key[r]     = asc ? mn : mx;
                key[r + J] = asc ? mx : mn;
            }
        }
    }
}

template<int R>
__device__ __forceinline__ void bitonic_sort_warp(unsigned* key) {
    const int lane = threadIdx.x & 31;
    const int N = 32 * R;
    for (int k = 2; k <= N; k <<= 1) {
        for (int m = (k >> 1) / R; m >= 1; m >>= 1) {
            #pragma unroll
            for (int r = 0; r < R; r++) {
                unsigned a = key[r];
                unsigned b = __shfl_xor_sync(0xffffffffu, a, m);
                bool asc   = (((unsigned)(lane * R + r) & (unsigned)k) == 0);
                bool lower = ((lane & m) == 0);
                unsigned mn = a < b ? a : b;
                unsigned mx = a < b ? b : a;
                key[r] = (lower == asc) ? mn : mx;
            }
        }
        inreg_pass<R, 8>(key, lane, k);
        inreg_pass<R, 4>(key, lane, k);
        inreg_pass<R, 2>(key, lane, k);
        inreg_pass<R, 1>(key, lane, k);
    }
}

// Ascending bitonic MERGE of a 32-element bitonic sequence (one value/lane).
__device__ __forceinline__ unsigned bitonic_merge32(unsigned v) {
    const int lane = threadIdx.x & 31;
    #pragma unroll
    for (int m = 16; m >= 1; m >>= 1) {
        unsigned b = __shfl_xor_sync(0xffffffffu, v, m);
        bool lower = ((lane & m) == 0);
        unsigned mn = v < b ? v : b;
        unsigned mx = v < b ? b : v;
        v = lower ? mn : mx;
    }
    return v;
}

// Merge two sorted-asc 32-lists: keep lowest (keep_min) or highest 32,
// result sorted ascending. a = A[lane], b = B[31-lane] (caller loads).
__device__ __forceinline__ unsigned merge32_step(unsigned a, unsigned b, bool keep_min) {
    unsigned v = keep_min ? (a < b ? a : b) : (a > b ? a : b);  // bitonic seq
    return bitonic_merge32(v);
}

// ---------------------------------------------------------------------------
// Mega-fused kernel: 256-thread blocks (8 warps), ONE row per block.
// KEY CHANGE vs full sort: only the top-32 and bottom-32 of each row are
// selected (local 64-sorts + 3-level pairwise merge trees; min-tree on warps
// 0-3, max-tree on warps 4-7 in parallel). Walks probe <=32 candidates; an
// exact dense-scan fallback (P ~ 2^-32 per node) preserves correctness.
// ---------------------------------------------------------------------------
__global__ void __launch_bounds__(256) mega_kernel(const float* __restrict__ x,
                                                   float* __restrict__ out) {
    __shared__ unsigned      bufA[NIN];     // 2 KB — lists / tree levels
    __shared__ unsigned      bufB[NIN];     // 2 KB
    __shared__ float         vals[NIN];     // 2 KB
    __shared__ float         hrow[NHID];    // 1 KB
    __shared__ unsigned      sMin[32];      // bottom-32 keys, sorted asc
    __shared__ unsigned      sMax[32];      // top-32 keys, sorted asc
    __shared__ unsigned char sel1[NHID];
    __shared__ unsigned char sel2[NIN];

    const int tid  = threadIdx.x;      // 0..255
    const int w    = tid >> 5;         // warp 0..7
    const int lane = tid & 31;
    const int row  = blockIdx.x;

    // ============ Layer-1: local 64-sorts (all ascending) ====================
    {
        unsigned key[2];
        const float* src = x + (size_t)row * NIN + w * 64 + lane * 2;
        float2 v = *(const float2*)src;
        *(float2*)(&vals[w * 64 + lane * 2]) = v;
        key[0] = (__float_as_uint(v.x) & ~(unsigned)(NIN - 1)) | (unsigned)(w * 64 + lane * 2);
        key[1] = (__float_as_uint(v.y) & ~(unsigned)(NIN - 1)) | (unsigned)(w * 64 + lane * 2 + 1);

        if (tid < 64)  ((unsigned*)sel1)[tid] = ((const unsigned*)g_sel1)[tid];
        if (tid < 128) ((unsigned*)sel2)[tid] = ((const unsigned*)g_sel2)[tid];

        bitonic_sort_warp<2>(key);
        bufA[w * 64 + lane * 2]     = key[0];
        bufA[w * 64 + lane * 2 + 1] = key[1];
    }
    __syncthreads();

    // ---- Level 1: 4 pair-merges of low-32s (warps 0-3) | high-32s (4-7) -----
    if (w < 4) {
        unsigned a = bufA[(2 * w) * 64 + lane];
        unsigned b = bufA[(2 * w + 1) * 64 + 31 - lane];
        bufB[w * 32 + lane] = merge32_step(a, b, true);
    } else {
        int m = w - 4;
        unsigned a = bufA[(2 * m) * 64 + 32 + lane];
        unsigned b = bufA[(2 * m + 1) * 64 + 63 - lane];
        bufB[256 + m * 32 + lane] = merge32_step(a, b, false);
    }
    __syncthreads();

    // ---- Level 2 -------------------------------------------------------------
    if (w == 0 || w == 1) {
        unsigned a = bufB[(2 * w) * 32 + lane];
        unsigned b = bufB[(2 * w + 1) * 32 + 31 - lane];
        bufA[w * 32 + lane] = merge32_step(a, b, true);
    } else if (w == 4 || w == 5) {
        int m = w - 4;
        unsigned a = bufB[256 + (2 * m) * 32 + lane];
        unsigned b = bufB[256 + (2 * m + 1) * 32 + 31 - lane];
        bufA[256 + m * 32 + lane] = merge32_step(a, b, false);
    }
    __syncthreads();

    // ---- Level 3 -> sMin / sMax ----------------------------------------------
    if (w == 0) {
        sMin[lane] = merge32_step(bufA[lane], bufA[63 - lane], true);
    } else if (w == 4) {
        sMax[lane] = merge32_step(bufA[256 + lane], bufA[256 + 63 - lane], false);
    }
    __syncthreads();

    // ============ Layer-1 walk: node = tid, <=32 probes + exact fallback =====
    {
        const int node = tid;
        const bool s = sel1[node] != 0;
        float v = s ? 0.0f : 1.0f;     // empty-mask identity
        bool  f = false;
        for (int t = 0; t < 32 && !f; t++) {
            unsigned kk = s ? sMax[31 - t] : sMin[t];
            int idx = (int)(kk & (unsigned)(NIN - 1));
            unsigned m = g_mT1[(idx >> 5) * NHID + node];   // coalesced, L1-resident
            if ((m >> (idx & 31)) & 1u) { v = vals[idx]; f = true; }
        }
        if (!f) {   // P ~ 2^-32 per node: exact dense masked scan
            for (int i = 0; i < NIN; i++)
                if ((g_mT1[(i >> 5) * NHID + node] >> (i & 31)) & 1u)
                    v = s ? fmaxf(v, vals[i]) : fminf(v, vals[i]);
        }
        hrow[node] = fmaxf(v, 0.0f);
    }
    __syncthreads();

    // ============ Layer-2: local 32-sorts + selection trees ===================
    {
        unsigned k2[1];
        int c = w * 32 + lane;
        k2[0] = (__float_as_uint(hrow[c]) & ~(unsigned)(NHID - 1)) | (unsigned)c;
        bitonic_sort_warp<1>(k2);
        bufA[w * 32 + lane] = k2[0];
    }
    __syncthreads();

    // ---- Level 1: top/bot-32 of each warp pair's 64 ---------------------------
    if (w < 4) {
        unsigned a = bufA[(2 * w) * 32 + lane];
        unsigned b = bufA[(2 * w + 1) * 32 + 31 - lane];
        bufB[w * 32 + lane] = merge32_step(a, b, true);
    } else {
        int m = w - 4;
        unsigned a = bufA[(2 * m) * 32 + lane];
        unsigned b = bufA[(2 * m + 1) * 32 + 31 - lane];
        bufB[256 + m * 32 + lane] = merge32_step(a, b, false);
    }
    __syncthreads();

    // ---- Level 2 ---------------------------------------------------------------
    if (w == 0 || w == 1) {
        unsigned a = bufB[(2 * w) * 32 + lane];
        unsigned b = bufB[(2 * w + 1) * 32 + 31 - lane];
        bufA[w * 32 + lane] = merge32_step(a, b, true);
    } else if (w == 4 || w == 5) {
        int m = w - 4;
        unsigned a = bufB[256 + (2 * m) * 32 + lane];
        unsigned b = bufB[256 + (2 * m + 1) * 32 + 31 - lane];
        bufA[256 + m * 32 + lane] = merge32_step(a, b, false);
    }
    __syncthreads();

    // ---- Level 3 -> sMin / sMax --------------------------------------------------
    if (w == 0) {
        sMin[lane] = merge32_step(bufA[lane], bufA[63 - lane], true);
    } else if (w == 4) {
        sMax[lane] = merge32_step(bufA[256 + lane], bufA[256 + 63 - lane], false);
    }
    __syncthreads();

    // ============ Layer-2 walk: 2 nodes/thread, <=32 probes + fallback ========
    {
        #pragma unroll
        for (int c = 0; c < 2; c++) {
            const int node = c * 256 + tid;
            const bool s = sel2[node] != 0;
            float v = s ? 0.0f : 1.0f;
            bool  f = false;
            for (int t = 0; t < 32 && !f; t++) {
                unsigned kk = s ? sMax[31 - t] : sMin[t];
                int idx = (int)(kk & (unsigned)(NHID - 1));
                unsigned m = g_mT2[(idx >> 5) * NIN + node];    // L1-resident
                if ((m >> (idx & 31)) & 1u) { v = hrow[idx]; f = true; }
            }
            if (!f) {
                for (int i = 0; i < NHID; i++)
                    if ((g_mT2[(i >> 5) * NIN + node] >> (i & 31)) & 1u)
                        v = s ? fmaxf(v, hrow[i]) : fminf(v, hrow[i]);
            }
            out[(size_t)row * NIN + node] = fmaxf(v, 0.0f);
        }
    }
}

// ---------------------------------------------------------------------------
// kernel_launch: prep (masks + sel) -> mega (both layers). Two launches.
// ---------------------------------------------------------------------------
extern "C" void kernel_launch(void* const* d_in, const int* in_sizes, int n_in,
                              void* d_out, int out_size) {
    const float* x       = (const float*)d_in[0];
    const float* logits1 = (const float*)d_in[1];
    const float* u1      = (const float*)d_in[2];
    const float* logits2 = (const float*)d_in[3];
    const float* u2      = (const float*)d_in[4];
    const void*  mask1   = d_in[5];
    const void*  mask2   = d_in[6];
    float* out = (float*)d_out;
    (void)in_sizes; (void)n_in; (void)out_size;

    prep_kernel<<<257, 256>>>(mask1, mask2, logits1, u1, logits2, u2);
    mega_kernel<<<BATCH, 256>>>(x, out);
}

// round 16
// speedup vs baseline: 1.2365x; 1.1155x over previous
#include <cuda_runtime.h>
#include <math.h>

#define BATCH 1024
#define NIN   512
#define NHID  256

// ---------------------------------------------------------------------------
// Device-global scratch (no allocation allowed anywhere).
// ---------------------------------------------------------------------------
__device__ unsigned      g_mT1[16 * NHID];   // transposed bitmask [w][node], layer1
__device__ unsigned      g_mT2[8 * NIN];     // transposed bitmask [w][node], layer2
__device__ unsigned char g_sel1[NHID];       // 1 = max-node, 0 = min-node
__device__ unsigned char g_sel2[NIN];

// ---------------------------------------------------------------------------
// Gumbel hard-select: forward value is exactly one-hot of argmax(logits + g).
// ---------------------------------------------------------------------------
__device__ __forceinline__ float gumbel_f(float u) {
    u = fminf(fmaxf(u, 1e-10f), 1.0f);
    return -logf(-logf(u));
}

// Per-warp mask dtype detection: 2 lane-parallel loads + ballots.
__device__ __forceinline__ int warp_detect(const void* p, int lane) {
    const unsigned* pw = (const unsigned*)p;
    unsigned a = pw[lane], b = pw[lane + 32];
    bool i32 = (a <= 1u) && (b <= 1u);
    bool f32 = (a == 0u || a == 0x3F800000u) && (b == 0u || b == 0x3F800000u);
    i32 = __all_sync(0xffffffffu, i32);
    f32 = __all_sync(0xffffffffu, f32);
    return i32 ? 2 : (f32 ? 3 : 1);
}

__device__ __forceinline__ bool mask_at(const void* p, int mode, int e) {
    if (mode == 2) return ((const int*)p)[e] != 0;
    if (mode == 3) return ((const float*)p)[e] != 0.0f;
    return ((const unsigned char*)p)[e] != 0;
}

// Prep: blocks 0..255 pack masks (one warp -> 4 words, coalesced + MLP),
// dtype detected ONCE per block (warps 0/1) and broadcast through smem;
// block 256 computes node sel for both layers.
__global__ void __launch_bounds__(256) prep_kernel(const void* __restrict__ m1,
                                                   const void* __restrict__ m2,
                                                   const float* __restrict__ logits1,
                                                   const float* __restrict__ u1,
                                                   const float* __restrict__ logits2,
                                                   const float* __restrict__ u2) {
    if (blockIdx.x == 256) {
        int n = threadIdx.x;
        {
            float z0 = logits1[2 * n]     + gumbel_f(u1[2 * n]);
            float z1 = logits1[2 * n + 1] + gumbel_f(u1[2 * n + 1]);
            g_sel1[n] = (z1 > z0) ? 1 : 0;
        }
        #pragma unroll
        for (int q = 0; q < 2; q++) {
            int j = q * 256 + n;
            float z0 = logits2[2 * j]     + gumbel_f(u2[2 * j]);
            float z1 = logits2[2 * j + 1] + gumbel_f(u2[2 * j + 1]);
            g_sel2[j] = (z1 > z0) ? 1 : 0;
        }
        return;
    }
    __shared__ int modes[2];
    const int wb   = threadIdx.x >> 5;        // warp within block
    const int lane = threadIdx.x & 31;
    if (wb == 0 && lane < 32) { int m = warp_detect(m1, lane); if (lane == 0) modes[0] = m; }
    if (wb == 1)              { int m = warp_detect(m2, lane); if (lane == 0) modes[1] = m; }
    __syncthreads();
    const int gw = blockIdx.x * 8 + wb;       // 0..2047
    if (gw < 1024) {
        const int mode = modes[0];
        #pragma unroll
        for (int q = 0; q < 4; q++) {
            int wi = gw * 4 + q;
            int node = wi >> 4, w = wi & 15;
            bool b = mask_at(m1, mode, node * NIN + w * 32 + lane);
            unsigned bits = __ballot_sync(0xffffffffu, b);
            if (lane == 0) g_mT1[w * NHID + node] = bits;
        }
    } else {
        const int mode = modes[1];
        #pragma unroll
        for (int q = 0; q < 4; q++) {
            int wi = (gw - 1024) * 4 + q;
            int node = wi >> 3, w = wi & 7;
            bool b = mask_at(m2, mode, node * NHID + w * 32 + lane);
            unsigned bits = __ballot_sync(0xffffffffu, b);
            if (lane == 0) g_mT2[w * NIN + node] = bits;
        }
    }
}

// ---------------------------------------------------------------------------
// Warp bitonic sort of 32*R u32 keys, ascending. Element i = lane*R + r.
// In-register passes exist ONLY for J < R (compile-time guarded).
// ---------------------------------------------------------------------------
template<int R, int J>
__device__ __forceinline__ void inreg_pass(unsigned* key, int lane, int k) {
    if constexpr (J < R) {
        if (2 * J > k) return;
        #pragma unroll
        for (int r = 0; r < R; r++) {
            if ((r & J) == 0) {
                bool asc = (((unsigned)(lane * R + r) & (unsigned)k) == 0);
                unsigned a = key[r], b = key[r + J];
                unsigned mn = a < b ? a : b;
                unsigned mx = a < b ? b : a;
                key[r]     = asc ? mn : mx;
                key[r + J] = asc ? mx : mn;
            }
        }
    }
}

template<int R>
__device__ __forceinline__ void bitonic_sort_warp(unsigned* key) {
    const int lane = threadIdx.x & 31;
    const int N = 32 * R;
    for (int k = 2; k <= N; k <<= 1) {
        for (int m = (k >> 1) / R; m >= 1; m >>= 1) {
            #pragma unroll
            for (int r = 0; r < R; r++) {
                unsigned a = key[r];
                unsigned b = __shfl_xor_sync(0xffffffffu, a, m);
                bool asc   = (((unsigned)(lane * R + r) & (unsigned)k) == 0);
                bool lower = ((lane & m) == 0);
                unsigned mn = a < b ? a : b;
                unsigned mx = a < b ? b : a;
                key[r] = (lower == asc) ? mn : mx;
            }
        }
        inreg_pass<R, 8>(key, lane, k);
        inreg_pass<R, 4>(key, lane, k);
        inreg_pass<R, 2>(key, lane, k);
        inreg_pass<R, 1>(key, lane, k);
    }
}

// Ascending bitonic MERGE of a 32-element bitonic sequence (one value/lane).
__device__ __forceinline__ unsigned bitonic_merge32(unsigned v) {
    const int lane = threadIdx.x & 31;
    #pragma unroll
    for (int m = 16; m >= 1; m >>= 1) {
        unsigned b = __shfl_xor_sync(0xffffffffu, v, m);
        bool lower = ((lane & m) == 0);
        unsigned mn = v < b ? v : b;
        unsigned mx = v < b ? b : v;
        v = lower ? mn : mx;
    }
    return v;
}

// Merge two sorted-asc 32-lists: keep lowest (keep_min) or highest 32,
// result sorted ascending. a = A[lane], b = B[31-lane] (caller loads).
__device__ __forceinline__ unsigned merge32_step(unsigned a, unsigned b, bool keep_min) {
    unsigned v = keep_min ? (a < b ? a : b) : (a > b ? a : b);  // bitonic seq
    return bitonic_merge32(v);
}

// ---------------------------------------------------------------------------
// Mega-fused kernel: 256-thread blocks (8 warps), ONE row per block.
// Top-32/bottom-32 selection (local 64-sorts + 3-level pairwise merge trees;
// min-tree on warps 0-3, max-tree on warps 4-7 in parallel). Walks probe
// <=32 candidates with a 2-probe unroll (2 LDG chains in flight); exact
// dense-scan fallback (P ~ 2^-32 per node) preserves correctness.
// ---------------------------------------------------------------------------
__global__ void __launch_bounds__(256) mega_kernel(const float* __restrict__ x,
                                                   float* __restrict__ out) {
    __shared__ unsigned      bufA[NIN];     // 2 KB — lists / tree levels
    __shared__ unsigned      bufB[NIN];     // 2 KB
    __shared__ float         vals[NIN];     // 2 KB
    __shared__ float         hrow[NHID];    // 1 KB
    __shared__ unsigned      sMin[32];      // bottom-32 keys, sorted asc
    __shared__ unsigned      sMax[32];      // top-32 keys, sorted asc
    __shared__ unsigned char sel1[NHID];
    __shared__ unsigned char sel2[NIN];

    const int tid  = threadIdx.x;      // 0..255
    const int w    = tid >> 5;         // warp 0..7
    const int lane = tid & 31;
    const int row  = blockIdx.x;

    // ============ Layer-1: local 64-sorts (all ascending) ====================
    {
        unsigned key[2];
        const float* src = x + (size_t)row * NIN + w * 64 + lane * 2;
        float2 v = *(const float2*)src;
        *(float2*)(&vals[w * 64 + lane * 2]) = v;
        key[0] = (__float_as_uint(v.x) & ~(unsigned)(NIN - 1)) | (unsigned)(w * 64 + lane * 2);
        key[1] = (__float_as_uint(v.y) & ~(unsigned)(NIN - 1)) | (unsigned)(w * 64 + lane * 2 + 1);

        if (tid < 64)  ((unsigned*)sel1)[tid] = ((const unsigned*)g_sel1)[tid];
        if (tid < 128) ((unsigned*)sel2)[tid] = ((const unsigned*)g_sel2)[tid];

        bitonic_sort_warp<2>(key);
        bufA[w * 64 + lane * 2]     = key[0];
        bufA[w * 64 + lane * 2 + 1] = key[1];
    }
    __syncthreads();

    // ---- Level 1: 4 pair-merges of low-32s (warps 0-3) | high-32s (4-7) -----
    if (w < 4) {
        unsigned a = bufA[(2 * w) * 64 + lane];
        unsigned b = bufA[(2 * w + 1) * 64 + 31 - lane];
        bufB[w * 32 + lane] = merge32_step(a, b, true);
    } else {
        int m = w - 4;
        unsigned a = bufA[(2 * m) * 64 + 32 + lane];
        unsigned b = bufA[(2 * m + 1) * 64 + 63 - lane];
        bufB[256 + m * 32 + lane] = merge32_step(a, b, false);
    }
    __syncthreads();

    // ---- Level 2 -------------------------------------------------------------
    if (w == 0 || w == 1) {
        unsigned a = bufB[(2 * w) * 32 + lane];
        unsigned b = bufB[(2 * w + 1) * 32 + 31 - lane];
        bufA[w * 32 + lane] = merge32_step(a, b, true);
    } else if (w == 4 || w == 5) {
        int m = w - 4;
        unsigned a = bufB[256 + (2 * m) * 32 + lane];
        unsigned b = bufB[256 + (2 * m + 1) * 32 + 31 - lane];
        bufA[256 + m * 32 + lane] = merge32_step(a, b, false);
    }
    __syncthreads();

    // ---- Level 3 -> sMin / sMax ----------------------------------------------
    if (w == 0) {
        sMin[lane] = merge32_step(bufA[lane], bufA[63 - lane], true);
    } else if (w == 4) {
        sMax[lane] = merge32_step(bufA[256 + lane], bufA[256 + 63 - lane], false);
    }
    __syncthreads();

    // ============ Layer-1 walk: node = tid, 2-probe unroll + fallback ========
    {
        const int node = tid;
        const bool s = sel1[node] != 0;
        float v = s ? 0.0f : 1.0f;     // empty-mask identity
        bool  f = false;
        for (int t = 0; t < 32 && !f; t += 2) {
            unsigned k0 = s ? sMax[31 - t] : sMin[t];
            unsigned k1 = s ? sMax[30 - t] : sMin[t + 1];
            int i0 = (int)(k0 & (unsigned)(NIN - 1));
            int i1 = (int)(k1 & (unsigned)(NIN - 1));
            unsigned m0 = g_mT1[(i0 >> 5) * NHID + node];   // coalesced, L1-resident
            unsigned m1 = g_mT1[(i1 >> 5) * NHID + node];
            bool h0 = (m0 >> (i0 & 31)) & 1u;
            bool h1 = (m1 >> (i1 & 31)) & 1u;
            if (h0)      { v = vals[i0]; f = true; }
            else if (h1) { v = vals[i1]; f = true; }
        }
        if (!f) {   // P ~ 2^-32 per node: exact dense masked scan
            for (int i = 0; i < NIN; i++)
                if ((g_mT1[(i >> 5) * NHID + node] >> (i & 31)) & 1u)
                    v = s ? fmaxf(v, vals[i]) : fminf(v, vals[i]);
        }
        hrow[node] = fmaxf(v, 0.0f);
    }
    __syncthreads();

    // ============ Layer-2: local 32-sorts + selection trees ===================
    {
        unsigned k2[1];
        int c = w * 32 + lane;
        k2[0] = (__float_as_uint(hrow[c]) & ~(unsigned)(NHID - 1)) | (unsigned)c;
        bitonic_sort_warp<1>(k2);
        bufA[w * 32 + lane] = k2[0];
    }
    __syncthreads();

    // ---- Level 1: top/bot-32 of each warp pair's 64 ---------------------------
    if (w < 4) {
        unsigned a = bufA[(2 * w) * 32 + lane];
        unsigned b = bufA[(2 * w + 1) * 32 + 31 - lane];
        bufB[w * 32 + lane] = merge32_step(a, b, true);
    } else {
        int m = w - 4;
        unsigned a = bufA[(2 * m) * 32 + lane];
        unsigned b = bufA[(2 * m + 1) * 32 + 31 - lane];
        bufB[256 + m * 32 + lane] = merge32_step(a, b, false);
    }
    __syncthreads();

    // ---- Level 2 ---------------------------------------------------------------
    if (w == 0 || w == 1) {
        unsigned a = bufB[(2 * w) * 32 + lane];
        unsigned b = bufB[(2 * w + 1) * 32 + 31 - lane];
        bufA[w * 32 + lane] = merge32_step(a, b, true);
    } else if (w == 4 || w == 5) {
        int m = w - 4;
        unsigned a = bufB[256 + (2 * m) * 32 + lane];
        unsigned b = bufB[256 + (2 * m + 1) * 32 + 31 - lane];
        bufA[256 + m * 32 + lane] = merge32_step(a, b, false);
    }
    __syncthreads();

    // ---- Level 3 -> sMin / sMax --------------------------------------------------
    if (w == 0) {
        sMin[lane] = merge32_step(bufA[lane], bufA[63 - lane], true);
    } else if (w == 4) {
        sMax[lane] = merge32_step(bufA[256 + lane], bufA[256 + 63 - lane], false);
    }
    __syncthreads();

    // ============ Layer-2 walk: 2 nodes/thread, 2-probe unroll + fallback =====
    {
        #pragma unroll
        for (int c = 0; c < 2; c++) {
            const int node = c * 256 + tid;
            const bool s = sel2[node] != 0;
            float v = s ? 0.0f : 1.0f;
            bool  f = false;
            for (int t = 0; t < 32 && !f; t += 2) {
                unsigned k0 = s ? sMax[31 - t] : sMin[t];
                unsigned k1 = s ? sMax[30 - t] : sMin[t + 1];
                int i0 = (int)(k0 & (unsigned)(NHID - 1));
                int i1 = (int)(k1 & (unsigned)(NHID - 1));
                unsigned m0 = g_mT2[(i0 >> 5) * NIN + node];    // L1-resident
                unsigned m1 = g_mT2[(i1 >> 5) * NIN + node];
                bool h0 = (m0 >> (i0 & 31)) & 1u;
                bool h1 = (m1 >> (i1 & 31)) & 1u;
                if (h0)      { v = hrow[i0]; f = true; }
                else if (h1) { v = hrow[i1]; f = true; }
            }
            if (!f) {
                for (int i = 0; i < NHID; i++)
                    if ((g_mT2[(i >> 5) * NIN + node] >> (i & 31)) & 1u)
                        v = s ? fmaxf(v, hrow[i]) : fminf(v, hrow[i]);
            }
            out[(size_t)row * NIN + node] = fmaxf(v, 0.0f);
        }
    }
}

// ---------------------------------------------------------------------------
// kernel_launch: prep (masks + sel) -> mega (both layers). Two launches.
// ---------------------------------------------------------------------------
extern "C" void kernel_launch(void* const* d_in, const int* in_sizes, int n_in,
                              void* d_out, int out_size) {
    const float* x       = (const float*)d_in[0];
    const float* logits1 = (const float*)d_in[1];
    const float* u1      = (const float*)d_in[2];
    const float* logits2 = (const float*)d_in[3];
    const float* u2      = (const float*)d_in[4];
    const void*  mask1   = d_in[5];
    const void*  mask2   = d_in[6];
    float* out = (float*)d_out;
    (void)in_sizes; (void)n_in; (void)out_size;

    prep_kernel<<<257, 256>>>(mask1, mask2, logits1, u1, logits2, u2);
    mega_kernel<<<BATCH, 256>>>(x, out);
}

// round 17
// speedup vs baseline: 1.2600x; 1.0190x over previous
#include <cuda_runtime.h>
#include <math.h>

#define BATCH 1024
#define NIN   512
#define NHID  256

// ---------------------------------------------------------------------------
// Device-global scratch (no allocation allowed anywhere).
// ---------------------------------------------------------------------------
__device__ unsigned      g_mT1[16 * NHID];   // transposed bitmask [w][node], layer1
__device__ unsigned      g_mT2[8 * NIN];     // transposed bitmask [w][node], layer2
__device__ unsigned char g_sel1[NHID];       // 1 = max-node, 0 = min-node
__device__ unsigned char g_sel2[NIN];

// ---------------------------------------------------------------------------
// Gumbel hard-select: forward value is exactly one-hot of argmax(logits + g).
// ---------------------------------------------------------------------------
__device__ __forceinline__ float gumbel_f(float u) {
    u = fminf(fmaxf(u, 1e-10f), 1.0f);
    return -logf(-logf(u));
}

// Per-warp mask dtype detection: 2 lane-parallel loads + ballots.
__device__ __forceinline__ int warp_detect(const void* p, int lane) {
    const unsigned* pw = (const unsigned*)p;
    unsigned a = pw[lane], b = pw[lane + 32];
    bool i32 = (a <= 1u) && (b <= 1u);
    bool f32 = (a == 0u || a == 0x3F800000u) && (b == 0u || b == 0x3F800000u);
    i32 = __all_sync(0xffffffffu, i32);
    f32 = __all_sync(0xffffffffu, f32);
    return i32 ? 2 : (f32 ? 3 : 1);
}

__device__ __forceinline__ bool mask_at(const void* p, int mode, int e) {
    if (mode == 2) return ((const int*)p)[e] != 0;
    if (mode == 3) return ((const float*)p)[e] != 0.0f;
    return ((const unsigned char*)p)[e] != 0;
}

// Prep: blocks 0..255 pack masks (one warp -> 4 words, coalesced + MLP),
// dtype detected ONCE per block (warps 0/1) and broadcast through smem;
// block 256 computes node sel for both layers.
__global__ void __launch_bounds__(256) prep_kernel(const void* __restrict__ m1,
                                                   const void* __restrict__ m2,
                                                   const float* __restrict__ logits1,
                                                   const float* __restrict__ u1,
                                                   const float* __restrict__ logits2,
                                                   const float* __restrict__ u2) {
    if (blockIdx.x == 256) {
        int n = threadIdx.x;
        {
            float z0 = logits1[2 * n]     + gumbel_f(u1[2 * n]);
            float z1 = logits1[2 * n + 1] + gumbel_f(u1[2 * n + 1]);
            g_sel1[n] = (z1 > z0) ? 1 : 0;
        }
        #pragma unroll
        for (int q = 0; q < 2; q++) {
            int j = q * 256 + n;
            float z0 = logits2[2 * j]     + gumbel_f(u2[2 * j]);
            float z1 = logits2[2 * j + 1] + gumbel_f(u2[2 * j + 1]);
            g_sel2[j] = (z1 > z0) ? 1 : 0;
        }
        return;
    }
    __shared__ int modes[2];
    const int wb   = threadIdx.x >> 5;        // warp within block
    const int lane = threadIdx.x & 31;
    if (wb == 0) { int m = warp_detect(m1, lane); if (lane == 0) modes[0] = m; }
    if (wb == 1) { int m = warp_detect(m2, lane); if (lane == 0) modes[1] = m; }
    __syncthreads();
    const int gw = blockIdx.x * 8 + wb;       // 0..2047
    if (gw < 1024) {
        const int mode = modes[0];
        #pragma unroll
        for (int q = 0; q < 4; q++) {
            int wi = gw * 4 + q;
            int node = wi >> 4, w = wi & 15;
            bool b = mask_at(m1, mode, node * NIN + w * 32 + lane);
            unsigned bits = __ballot_sync(0xffffffffu, b);
            if (lane == 0) g_mT1[w * NHID + node] = bits;
        }
    } else {
        const int mode = modes[1];
        #pragma unroll
        for (int q = 0; q < 4; q++) {
            int wi = (gw - 1024) * 4 + q;
            int node = wi >> 3, w = wi & 7;
            bool b = mask_at(m2, mode, node * NHID + w * 32 + lane);
            unsigned bits = __ballot_sync(0xffffffffu, b);
            if (lane == 0) g_mT2[w * NIN + node] = bits;
        }
    }
}

// ---------------------------------------------------------------------------
// Warp bitonic sort of 32*R u32 keys, ascending. Element i = lane*R + r.
// In-register passes exist ONLY for J < R (compile-time guarded).
// ---------------------------------------------------------------------------
template<int R, int J>
__device__ __forceinline__ void inreg_pass(unsigned* key, int lane, int k) {
    if constexpr (J < R) {
        if (2 * J > k) return;
        #pragma unroll
        for (int r = 0; r < R; r++) {
            if ((r & J) == 0) {
                bool asc = (((unsigned)(lane * R + r) & (unsigned)k) == 0);
                unsigned a = key[r], b = key[r + J];
                unsigned mn = a < b ? a : b;
                unsigned mx = a < b ? b : a;
                key[r]     = asc ? mn : mx;
                key[r + J] = asc ? mx : mn;
            }
        }
    }
}

template<int R>
__device__ __forceinline__ void bitonic_sort_warp(unsigned* key) {
    const int lane = threadIdx.x & 31;
    const int N = 32 * R;
    for (int k = 2; k <= N; k <<= 1) {
        for (int m = (k >> 1) / R; m >= 1; m >>= 1) {
            #pragma unroll
            for (int r = 0; r < R; r++) {
                unsigned a = key[r];
                unsigned b = __shfl_xor_sync(0xffffffffu, a, m);
                bool asc   = (((unsigned)(lane * R + r) & (unsigned)k) == 0);
                bool lower = ((lane & m) == 0);
                unsigned mn = a < b ? a : b;
                unsigned mx = a < b ? b : a;
                key[r] = (lower == asc) ? mn : mx;
            }
        }
        inreg_pass<R, 8>(key, lane, k);
        inreg_pass<R, 4>(key, lane, k);
        inreg_pass<R, 2>(key, lane, k);
        inreg_pass<R, 1>(key, lane, k);
    }
}

// Ascending bitonic MERGE of a 32-element bitonic sequence (one value/lane).
__device__ __forceinline__ unsigned bitonic_merge32(unsigned v) {
    const int lane = threadIdx.x & 31;
    #pragma unroll
    for (int m = 16; m >= 1; m >>= 1) {
        unsigned b = __shfl_xor_sync(0xffffffffu, v, m);
        bool lower = ((lane & m) == 0);
        unsigned mn = v < b ? v : b;
        unsigned mx = v < b ? b : v;
        v = lower ? mn : mx;
    }
    return v;
}

// Merge two sorted-asc 32-lists: keep lowest (keep_min) or highest 32,
// result sorted ascending. a = A[lane], b = B[31-lane] (caller loads).
__device__ __forceinline__ unsigned merge32_step(unsigned a, unsigned b, bool keep_min) {
    unsigned v = keep_min ? (a < b ? a : b) : (a > b ? a : b);  // bitonic seq
    return bitonic_merge32(v);
}

// ---------------------------------------------------------------------------
// Mega-fused kernel: 512-thread blocks (16 warps), TWO rows per block, grid
// 512. Every barrier serves two rows; selection trees fill more warps
// (level 1: 16/16, level 2: 8/16, level 3: 4/16). Per-row logic identical to
// the proven R15/R16 kernel, with a row-offset indexing layer.
// ---------------------------------------------------------------------------
__global__ void __launch_bounds__(512) mega_kernel(const float* __restrict__ x,
                                                   float* __restrict__ out) {
    __shared__ unsigned      bufA[2][NIN];   // 4 KB — lists / tree levels
    __shared__ unsigned      bufB[2][NIN];   // 4 KB
    __shared__ float         vals[2][NIN];   // 4 KB
    __shared__ float         hrow[2][NHID];  // 2 KB
    __shared__ unsigned      sMin[2][32];    // bottom-32 keys, sorted asc
    __shared__ unsigned      sMax[2][32];    // top-32 keys, sorted asc
    __shared__ unsigned char sel1[NHID];
    __shared__ unsigned char sel2[NIN];

    const int tid  = threadIdx.x;      // 0..511
    const int w    = tid >> 5;         // warp 0..15
    const int lane = tid & 31;
    const int wr   = w >> 3;           // row within block (0/1)
    const int wl   = w & 7;            // warp within row (0..7)
    const int tr   = wl * 32 + lane;   // thread within row (0..255)
    const int row  = blockIdx.x * 2 + wr;

    // ============ Layer-1: local 64-sorts (all ascending), per row ===========
    {
        unsigned key[2];
        const float* src = x + (size_t)row * NIN + wl * 64 + lane * 2;
        float2 v = *(const float2*)src;
        *(float2*)(&vals[wr][wl * 64 + lane * 2]) = v;
        key[0] = (__float_as_uint(v.x) & ~(unsigned)(NIN - 1)) | (unsigned)(wl * 64 + lane * 2);
        key[1] = (__float_as_uint(v.y) & ~(unsigned)(NIN - 1)) | (unsigned)(wl * 64 + lane * 2 + 1);

        if (tid < 64)  ((unsigned*)sel1)[tid] = ((const unsigned*)g_sel1)[tid];
        if (tid < 128) ((unsigned*)sel2)[tid] = ((const unsigned*)g_sel2)[tid];

        bitonic_sort_warp<2>(key);
        bufA[wr][wl * 64 + lane * 2]     = key[0];
        bufA[wr][wl * 64 + lane * 2 + 1] = key[1];
    }
    __syncthreads();

    // ---- Level 1: per row, 4 min-merges (wl 0-3) | 4 max-merges (wl 4-7) ----
    if (wl < 4) {
        unsigned a = bufA[wr][(2 * wl) * 64 + lane];
        unsigned b = bufA[wr][(2 * wl + 1) * 64 + 31 - lane];
        bufB[wr][wl * 32 + lane] = merge32_step(a, b, true);
    } else {
        int m = wl - 4;
        unsigned a = bufA[wr][(2 * m) * 64 + 32 + lane];
        unsigned b = bufA[wr][(2 * m + 1) * 64 + 63 - lane];
        bufB[wr][256 + m * 32 + lane] = merge32_step(a, b, false);
    }
    __syncthreads();

    // ---- Level 2 -------------------------------------------------------------
    if (wl == 0 || wl == 1) {
        unsigned a = bufB[wr][(2 * wl) * 32 + lane];
        unsigned b = bufB[wr][(2 * wl + 1) * 32 + 31 - lane];
        bufA[wr][wl * 32 + lane] = merge32_step(a, b, true);
    } else if (wl == 4 || wl == 5) {
        int m = wl - 4;
        unsigned a = bufB[wr][256 + (2 * m) * 32 + lane];
        unsigned b = bufB[wr][256 + (2 * m + 1) * 32 + 31 - lane];
        bufA[wr][256 + m * 32 + lane] = merge32_step(a, b, false);
    }
    __syncthreads();

    // ---- Level 3 -> sMin / sMax ----------------------------------------------
    if (wl == 0) {
        sMin[wr][lane] = merge32_step(bufA[wr][lane], bufA[wr][63 - lane], true);
    } else if (wl == 4) {
        sMax[wr][lane] = merge32_step(bufA[wr][256 + lane], bufA[wr][256 + 63 - lane], false);
    }
    __syncthreads();

    // ============ Layer-1 walk: node = tr, 2-probe unroll + fallback =========
    {
        const int node = tr;
        const bool s = sel1[node] != 0;
        float v = s ? 0.0f : 1.0f;     // empty-mask identity
        bool  f = false;
        for (int t = 0; t < 32 && !f; t += 2) {
            unsigned k0 = s ? sMax[wr][31 - t] : sMin[wr][t];
            unsigned k1 = s ? sMax[wr][30 - t] : sMin[wr][t + 1];
            int i0 = (int)(k0 & (unsigned)(NIN - 1));
            int i1 = (int)(k1 & (unsigned)(NIN - 1));
            unsigned m0 = g_mT1[(i0 >> 5) * NHID + node];   // coalesced, L1-resident
            unsigned m1 = g_mT1[(i1 >> 5) * NHID + node];
            bool h0 = (m0 >> (i0 & 31)) & 1u;
            bool h1 = (m1 >> (i1 & 31)) & 1u;
            if (h0)      { v = vals[wr][i0]; f = true; }
            else if (h1) { v = vals[wr][i1]; f = true; }
        }
        if (!f) {   // P ~ 2^-32 per node: exact dense masked scan
            for (int i = 0; i < NIN; i++)
                if ((g_mT1[(i >> 5) * NHID + node] >> (i & 31)) & 1u)
                    v = s ? fmaxf(v, vals[wr][i]) : fminf(v, vals[wr][i]);
        }
        hrow[wr][node] = fmaxf(v, 0.0f);
    }
    __syncthreads();

    // ============ Layer-2: local 32-sorts + selection trees ===================
    {
        unsigned k2[1];
        int c = wl * 32 + lane;
        k2[0] = (__float_as_uint(hrow[wr][c]) & ~(unsigned)(NHID - 1)) | (unsigned)c;
        bitonic_sort_warp<1>(k2);
        bufA[wr][wl * 32 + lane] = k2[0];
    }
    __syncthreads();

    // ---- Level 1: top/bot-32 of each warp pair's 64 ---------------------------
    if (wl < 4) {
        unsigned a = bufA[wr][(2 * wl) * 32 + lane];
        unsigned b = bufA[wr][(2 * wl + 1) * 32 + 31 - lane];
        bufB[wr][wl * 32 + lane] = merge32_step(a, b, true);
    } else {
        int m = wl - 4;
        unsigned a = bufA[wr][(2 * m) * 32 + lane];
        unsigned b = bufA[wr][(2 * m + 1) * 32 + 31 - lane];
        bufB[wr][256 + m * 32 + lane] = merge32_step(a, b, false);
    }
    __syncthreads();

    // ---- Level 2 ---------------------------------------------------------------
    if (wl == 0 || wl == 1) {
        unsigned a = bufB[wr][(2 * wl) * 32 + lane];
        unsigned b = bufB[wr][(2 * wl + 1) * 32 + 31 - lane];
        bufA[wr][wl * 32 + lane] = merge32_step(a, b, true);
    } else if (wl == 4 || wl == 5) {
        int m = wl - 4;
        unsigned a = bufB[wr][256 + (2 * m) * 32 + lane];
        unsigned b = bufB[wr][256 + (2 * m + 1) * 32 + 31 - lane];
        bufA[wr][256 + m * 32 + lane] = merge32_step(a, b, false);
    }
    __syncthreads();

    // ---- Level 3 -> sMin / sMax --------------------------------------------------
    if (wl == 0) {
        sMin[wr][lane] = merge32_step(bufA[wr][lane], bufA[wr][63 - lane], true);
    } else if (wl == 4) {
        sMax[wr][lane] = merge32_step(bufA[wr][256 + lane], bufA[wr][256 + 63 - lane], false);
    }
    __syncthreads();

    // ============ Layer-2 walk: 2 nodes/thread, 2-probe unroll + fallback =====
    {
        #pragma unroll
        for (int c = 0; c < 2; c++) {
            const int node = c * 256 + tr;
            const bool s = sel2[node] != 0;
            float v = s ? 0.0f : 1.0f;
            bool  f = false;
            for (int t = 0; t < 32 && !f; t += 2) {
                unsigned k0 = s ? sMax[wr][31 - t] : sMin[wr][t];
                unsigned k1 = s ? sMax[wr][30 - t] : sMin[wr][t + 1];
                int i0 = (int)(k0 & (unsigned)(NHID - 1));
                int i1 = (int)(k1 & (unsigned)(NHID - 1));
                unsigned m0 = g_mT2[(i0 >> 5) * NIN + node];    // L1-resident
                unsigned m1 = g_mT2[(i1 >> 5) * NIN + node];
                bool h0 = (m0 >> (i0 & 31)) & 1u;
                bool h1 = (m1 >> (i1 & 31)) & 1u;
                if (h0)      { v = hrow[wr][i0]; f = true; }
                else if (h1) { v = hrow[wr][i1]; f = true; }
            }
            if (!f) {
                for (int i = 0; i < NHID; i++)
                    if ((g_mT2[(i >> 5) * NIN + node] >> (i & 31)) & 1u)
                        v = s ? fmaxf(v, hrow[wr][i]) : fminf(v, hrow[wr][i]);
            }
            out[(size_t)row * NIN + node] = fmaxf(v, 0.0f);
        }
    }
}

// ---------------------------------------------------------------------------
// kernel_launch: prep (masks + sel) -> mega (both layers). Two launches.
// ---------------------------------------------------------------------------
extern "C" void kernel_launch(void* const* d_in, const int* in_sizes, int n_in,
                              void* d_out, int out_size) {
    const float* x       = (const float*)d_in[0];
    const float* logits1 = (const float*)d_in[1];
    const float* u1      = (const float*)d_in[2];
    const float* logits2 = (const float*)d_in[3];
    const float* u2      = (const float*)d_in[4];
    const void*  mask1   = d_in[5];
    const void*  mask2   = d_in[6];
    float* out = (float*)d_out;
    (void)in_sizes; (void)n_in; (void)out_size;

    prep_kernel<<<257, 256>>>(mask1, mask2, logits1, u1, logits2, u2);
    mega_kernel<<<BATCH / 2, 512>>>(x, out);
}